// round 14
// baseline (speedup 1.0000x reference)
#include <cuda_runtime.h>
#include <cuda_bf16.h>
#include <math.h>
#include <stdint.h>

// ---------------------------------------------------------------------------
// Problem constants
// ---------------------------------------------------------------------------
#define BWIN   4096
#define NTOK   49
#define CDIM   384
#define NHEAD  12
#define HD     32
#define NWMASK 64
#define TOKENS (BWIN * NTOK)   // 200704
#define QKV_COLS (3 * CDIM)    // 1152
#define NN (NTOK * NTOK)       // 2401

// Scratch (device globals; referenced ONLY from device code)
__device__ float g_q[(size_t)BWIN * NHEAD * NTOK * HD];
__device__ float g_k[(size_t)BWIN * NHEAD * NTOK * HD];
__device__ float g_v[(size_t)BWIN * NHEAD * NTOK * HD];
__device__ float g_mb[(size_t)NWMASK * NHEAD * NN];
__device__ __nv_bfloat16 g_xh[(size_t)TOKENS * CDIM];
__device__ __nv_bfloat16 g_xl[(size_t)TOKENS * CDIM];
__device__ __nv_bfloat16 g_wqh[(size_t)QKV_COLS * CDIM];
__device__ __nv_bfloat16 g_wql[(size_t)QKV_COLS * CDIM];
__device__ __nv_bfloat16 g_wph[(size_t)CDIM * CDIM];
__device__ __nv_bfloat16 g_wpl[(size_t)CDIM * CDIM];
__device__ __nv_bfloat16 g_ctxh[(size_t)TOKENS * CDIM];
__device__ __nv_bfloat16 g_ctxl[(size_t)TOKENS * CDIM];

// ---------------------------------------------------------------------------
// helpers
// ---------------------------------------------------------------------------
__device__ __forceinline__ uint32_t smem_to_u32(const void* smem_ptr) {
    uint32_t addr;
    asm("{ .reg .u64 tmp; cvta.to.shared.u64 tmp, %1; cvt.u32.u64 %0, tmp; }"
        : "=r"(addr) : "l"(smem_ptr));
    return addr;
}

__device__ __forceinline__ void ldsm4(uint32_t r[4], uint32_t addr) {
    asm volatile("ldmatrix.sync.aligned.m8n8.x4.shared.b16 {%0,%1,%2,%3}, [%4];"
        : "=r"(r[0]), "=r"(r[1]), "=r"(r[2]), "=r"(r[3]) : "r"(addr));
}

__device__ __forceinline__ void mma_bf16(float c[4], const uint32_t a[4],
                                         uint32_t b0, uint32_t b1) {
    asm volatile(
        "mma.sync.aligned.m16n8k16.row.col.f32.bf16.bf16.f32 "
        "{%0,%1,%2,%3}, {%4,%5,%6,%7}, {%8,%9}, {%0,%1,%2,%3};"
        : "+f"(c[0]), "+f"(c[1]), "+f"(c[2]), "+f"(c[3])
        : "r"(a[0]), "r"(a[1]), "r"(a[2]), "r"(a[3]), "r"(b0), "r"(b1));
}

#define CP_ASYNC_16(dst, src) \
    asm volatile("cp.async.ca.shared.global [%0], [%1], 16;" \
        :: "r"(dst), "l"(src) : "memory")
#define CP_COMMIT() asm volatile("cp.async.commit_group;" ::: "memory")
#define CP_WAITN(n) asm volatile("cp.async.wait_group %0;" :: "n"(n) : "memory")

// ---------------------------------------------------------------------------
// Prep: split fp32 arrays into bf16 hi/lo
// ---------------------------------------------------------------------------
template<int WHICH>
__global__ __launch_bounds__(256) void split_kernel(const float* __restrict__ src)
{
    const size_t count = (WHICH == 0) ? (size_t)TOKENS * CDIM
                       : (WHICH == 1) ? (size_t)QKV_COLS * CDIM
                                      : (size_t)CDIM * CDIM;
    __nv_bfloat16* __restrict__ dh = (WHICH == 0) ? g_xh : (WHICH == 1) ? g_wqh : g_wph;
    __nv_bfloat16* __restrict__ dl = (WHICH == 0) ? g_xl : (WHICH == 1) ? g_wql : g_wpl;

    const size_t i4 = (size_t)blockIdx.x * 256 + threadIdx.x;
    if (i4 * 4 >= count) return;
    float4 a = *(const float4*)&src[i4 * 4];
    __nv_bfloat16 h0 = __float2bfloat16(a.x), h1 = __float2bfloat16(a.y);
    __nv_bfloat16 h2 = __float2bfloat16(a.z), h3 = __float2bfloat16(a.w);
    __nv_bfloat16 l0 = __float2bfloat16(a.x - __bfloat162float(h0));
    __nv_bfloat16 l1 = __float2bfloat16(a.y - __bfloat162float(h1));
    __nv_bfloat16 l2 = __float2bfloat16(a.z - __bfloat162float(h2));
    __nv_bfloat16 l3 = __float2bfloat16(a.w - __bfloat162float(h3));
    uint2 hp, lp;
    hp.x = (uint32_t)__bfloat16_as_ushort(h0) | ((uint32_t)__bfloat16_as_ushort(h1) << 16);
    hp.y = (uint32_t)__bfloat16_as_ushort(h2) | ((uint32_t)__bfloat16_as_ushort(h3) << 16);
    lp.x = (uint32_t)__bfloat16_as_ushort(l0) | ((uint32_t)__bfloat16_as_ushort(l1) << 16);
    lp.y = (uint32_t)__bfloat16_as_ushort(l2) | ((uint32_t)__bfloat16_as_ushort(l3) << 16);
    *(uint2*)&dh[i4 * 4] = hp;
    *(uint2*)&dl[i4 * 4] = lp;
}

// ---------------------------------------------------------------------------
// Prep: g_mb[w][h][i*49+j] = mask[w][i][j] + bias_table[rel_index[i][j]][h]
// ---------------------------------------------------------------------------
__global__ __launch_bounds__(256) void prep_mb_kernel(
    const float* __restrict__ mask,
    const float* __restrict__ bias_table,
    const int*   __restrict__ rel_index)
{
    const int idx = blockIdx.x * 256 + threadIdx.x;
    if (idx >= NWMASK * NHEAD * NN) return;
    const int ij = idx % NN;
    const int wh = idx / NN;
    const int h = wh % NHEAD;
    const int w = wh / NHEAD;
    g_mb[idx] = mask[(size_t)w * NN + ij] + bias_table[rel_index[ij] * NHEAD + h];
}

// ---------------------------------------------------------------------------
// GEMM: 128(M) x 128(N) tile, K chunks of 16, 3-stage cp.async pipeline.
// 8 warps: wm=wid&1 (M64), wn=wid>>1 (N32). 3-term split-bf16 HMMA.
// ROWSTR=24 bf16 = 48B/row: 16B-aligned rows; ldsm row-start banks
// (12r mod 32) = {0,12,24,4,16,28,8,20} x 4-bank spans -> all 32, conflict-free.
// ---------------------------------------------------------------------------
#define TM 128
#define TN 128
#define KCH 16
#define NCH (CDIM / KCH)            // 24
#define ROWSTR 24                   // bf16 per smem row (48B)
#define BUF_SZ (128 * 48)           // 6144 per buffer
#define BUF_AH 0
#define BUF_AL (1 * BUF_SZ)
#define BUF_BH (2 * BUF_SZ)
#define BUF_BL (3 * BUF_SZ)
#define STAGE  (4 * BUF_SZ)         // 24576
#define NSTAGE 3
#define GEMM_SMEM (NSTAGE * STAGE)  // 73728

template<int MODE>
__global__ __launch_bounds__(256) void gemm_mma_kernel(
    const float* __restrict__ bias,
    float* __restrict__ Cout)
{
    const __nv_bfloat16* __restrict__ Ah = (MODE == 0) ? g_xh : g_ctxh;
    const __nv_bfloat16* __restrict__ Al = (MODE == 0) ? g_xl : g_ctxl;
    const __nv_bfloat16* __restrict__ Bh = (MODE == 0) ? g_wqh : g_wph;
    const __nv_bfloat16* __restrict__ Bl = (MODE == 0) ? g_wql : g_wpl;

    extern __shared__ char smem[];
    const uint32_t sb = smem_to_u32(smem);
    const int tid = threadIdx.x;
    const int wid = tid >> 5;
    const int lane = tid & 31;
    const int m0 = blockIdx.y * TM;
    const int n0 = blockIdx.x * TN;
    const int wm = wid & 1;
    const int wn = wid >> 1;
    const int g = lane >> 2;
    const int t = lane & 3;

    // cp.async coords: thread handles row tid>>1, 16B half tid&1 (128 rows x 32B)
    const int crow = tid >> 1;
    const int chalf = tid & 1;
    const uint32_t soff = (uint32_t)(crow * 48 + chalf * 16);
    const size_t goff = (size_t)crow * CDIM + chalf * 8;

    float acc[4][4][4];
#pragma unroll
    for (int i = 0; i < 4; i++)
#pragma unroll
        for (int j = 0; j < 4; j++)
#pragma unroll
            for (int k = 0; k < 4; k++) acc[i][j][k] = 0.f;

    // ldmatrix bases (within stage): A m16k16 x4; B n16k16 x4
    const uint32_t aAddrBase =
        ((uint32_t)((wm * 64 + (lane & 15)) * ROWSTR + (lane >> 4) * 8)) * 2;
    const uint32_t bAddrBase =
        ((uint32_t)((wn * 32 + (lane & 7) + ((lane >> 4) & 1) * 8) * ROWSTR
                    + ((lane >> 3) & 1) * 8)) * 2;

#define ISSUE_CHUNK(stb, k0) do { \
    CP_ASYNC_16((stb) + BUF_AH + soff, Ah + (size_t)m0 * CDIM + (k0) + goff); \
    CP_ASYNC_16((stb) + BUF_AL + soff, Al + (size_t)m0 * CDIM + (k0) + goff); \
    CP_ASYNC_16((stb) + BUF_BH + soff, Bh + (size_t)n0 * CDIM + (k0) + goff); \
    CP_ASYNC_16((stb) + BUF_BL + soff, Bl + (size_t)n0 * CDIM + (k0) + goff); \
    CP_COMMIT(); \
} while (0)

    ISSUE_CHUNK(sb, 0);
    ISSUE_CHUNK(sb + STAGE, KCH);

    for (int c = 0; c < NCH; c++) {
        if (c + 2 < NCH) {
            ISSUE_CHUNK(sb + (uint32_t)((c + 2) % NSTAGE) * STAGE, (c + 2) * KCH);
            CP_WAITN(2);
        } else if (c + 1 < NCH) {
            CP_WAITN(1);
        } else {
            CP_WAITN(0);
        }
        __syncthreads();

        const uint32_t stb = sb + (uint32_t)(c % NSTAGE) * STAGE;
        uint32_t bh[2][4], bl[2][4];
#pragma unroll
        for (int nt = 0; nt < 2; nt++) {
            const uint32_t baddr = stb + BUF_BH + bAddrBase
                + (uint32_t)(nt * 16 * ROWSTR) * 2;
            ldsm4(bh[nt], baddr);
            ldsm4(bl[nt], baddr + (BUF_BL - BUF_BH));
        }
#pragma unroll
        for (int mf = 0; mf < 4; mf++) {
            uint32_t ah[4], al[4];
            const uint32_t aaddr = stb + BUF_AH + aAddrBase
                + (uint32_t)(mf * 16 * ROWSTR) * 2;
            ldsm4(ah, aaddr);
            ldsm4(al, aaddr + (BUF_AL - BUF_AH));
#pragma unroll
            for (int nt = 0; nt < 2; nt++) {
#pragma unroll
                for (int nf = 0; nf < 2; nf++) {
                    mma_bf16(acc[mf][nt * 2 + nf], ah, bh[nt][nf * 2], bh[nt][nf * 2 + 1]);
                    mma_bf16(acc[mf][nt * 2 + nf], ah, bl[nt][nf * 2], bl[nt][nf * 2 + 1]);
                    mma_bf16(acc[mf][nt * 2 + nf], al, bh[nt][nf * 2], bh[nt][nf * 2 + 1]);
                }
            }
        }
        __syncthreads();
    }
#undef ISSUE_CHUNK

    const int rbase = m0 + wm * 64;
    const int colw = n0 + wn * 32;

#pragma unroll
    for (int mf = 0; mf < 4; mf++) {
#pragma unroll
        for (int nc = 0; nc < 4; nc++) {
            const int col = colw + nc * 8 + 2 * t;
            const float2 bs = *(const float2*)&bias[col];
            if (MODE == 0) {
                const int three = n0 / CDIM;
                const int colseg = col - three * CDIM;
                const int h = colseg >> 5;
                const int d = colseg & 31;
                float* __restrict__ dst = (three == 0) ? g_q : ((three == 1) ? g_k : g_v);
                const float sc = (three == 0) ? 0.17677669529663687f : 1.0f;
#pragma unroll
                for (int hf = 0; hf < 2; hf++) {
                    const int r = rbase + mf * 16 + g + hf * 8;
                    const int bw = r / NTOK;
                    const int n = r - bw * NTOK;
                    float2 o;
                    o.x = (acc[mf][nc][hf * 2 + 0] + bs.x) * sc;
                    o.y = (acc[mf][nc][hf * 2 + 1] + bs.y) * sc;
                    *(float2*)&dst[(((size_t)bw * NHEAD + h) * NTOK + n) * HD + d] = o;
                }
            } else {
#pragma unroll
                for (int hf = 0; hf < 2; hf++) {
                    const int r = rbase + mf * 16 + g + hf * 8;
                    float2 o;
                    o.x = acc[mf][nc][hf * 2 + 0] + bs.x;
                    o.y = acc[mf][nc][hf * 2 + 1] + bs.y;
                    *(float2*)&Cout[(size_t)r * CDIM + col] = o;
                }
            }
        }
    }
}

// ---------------------------------------------------------------------------
// Attention (R10 version — proven): row-major smem, register-blocked,
// fused mb table, bf16 hi/lo ctx output.
// ---------------------------------------------------------------------------
__global__ __launch_bounds__(256) void attn_kernel(void)
{
    const int bh = blockIdx.x;
    const int b = bh / NHEAD;
    const int h = bh - b * NHEAD;
    const int wmask = b & (NWMASK - 1);

    __shared__ float qs[52 * 33];   // rows 49..51 zeroed
    __shared__ float ks[NTOK * 33];
    __shared__ float vs[NTOK * 33];
    __shared__ float s[52 * 50];    // rows 49..51 zeroed

    const float* __restrict__ qg = g_q + (size_t)bh * NTOK * HD;
    const float* __restrict__ kg = g_k + (size_t)bh * NTOK * HD;
    const float* __restrict__ vg = g_v + (size_t)bh * NTOK * HD;
    const float* __restrict__ mb = g_mb + (size_t)(wmask * NHEAD + h) * NN;

    for (int idx = threadIdx.x; idx < NTOK * HD; idx += 256) {
        const int n = idx >> 5;
        const int d = idx & 31;
        qs[n * 33 + d] = qg[idx];
        ks[n * 33 + d] = kg[idx];
        vs[n * 33 + d] = vg[idx];
    }
    if (threadIdx.x < 99)  qs[49 * 33 + threadIdx.x] = 0.f;
    if (threadIdx.x < 150) s[49 * 50 + threadIdx.x] = 0.f;
    __syncthreads();

    const int warp = threadIdx.x >> 5;
    const int lane = threadIdx.x & 31;
    const int j1ok = (lane < NTOK - 32);

    for (int it = warp; it < 13; it += 8) {
        const int i0 = it * 4;
        float a0[4] = {0.f, 0.f, 0.f, 0.f};
        float a1[4] = {0.f, 0.f, 0.f, 0.f};
#pragma unroll
        for (int m = 0; m < HD; m++) {
            const float kv0 = ks[lane * 33 + m];
            const float kv1 = j1ok ? ks[(lane + 32) * 33 + m] : 0.f;
#pragma unroll
            for (int r = 0; r < 4; r++) {
                const float qv = qs[(i0 + r) * 33 + m];   // broadcast
                a0[r] += qv * kv0;
                a1[r] += qv * kv1;
            }
        }
#pragma unroll
        for (int r = 0; r < 4; r++) {
            const int i = i0 + r;
            if (i < NTOK) {
                s[i * 50 + lane] = a0[r] + mb[i * NTOK + lane];
                if (j1ok) s[i * 50 + lane + 32] = a1[r] + mb[i * NTOK + lane + 32];
            }
        }
    }
    __syncthreads();

    for (int i = warp; i < NTOK; i += 8) {
        float v0 = s[i * 50 + lane];
        float v1 = j1ok ? s[i * 50 + lane + 32] : -INFINITY;
        float mx = fmaxf(v0, v1);
#pragma unroll
        for (int o = 16; o > 0; o >>= 1)
            mx = fmaxf(mx, __shfl_xor_sync(0xFFFFFFFFu, mx, o));
        float e0 = __expf(v0 - mx);
        float e1 = j1ok ? __expf(v1 - mx) : 0.f;
        float sum = e0 + e1;
#pragma unroll
        for (int o = 16; o > 0; o >>= 1)
            sum += __shfl_xor_sync(0xFFFFFFFFu, sum, o);
        const float inv = 1.f / sum;
        s[i * 50 + lane] = e0 * inv;
        if (j1ok) s[i * 50 + lane + 32] = e1 * inv;
    }
    __syncthreads();

    __nv_bfloat16* __restrict__ ch = g_ctxh + ((size_t)b * NTOK) * CDIM + h * HD;
    __nv_bfloat16* __restrict__ cl = g_ctxl + ((size_t)b * NTOK) * CDIM + h * HD;
    for (int it = warp; it < 13; it += 8) {
        const int i0 = it * 4;
        float a[4] = {0.f, 0.f, 0.f, 0.f};
        for (int j = 0; j < NTOK; j++) {
            const float vv = vs[j * 33 + lane];
#pragma unroll
            for (int r = 0; r < 4; r++)
                a[r] += s[(i0 + r) * 50 + j] * vv;   // s broadcast
        }
#pragma unroll
        for (int r = 0; r < 4; r++) {
            const int i = i0 + r;
            if (i < NTOK) {
                const float val = a[r];
                const __nv_bfloat16 hi = __float2bfloat16(val);
                const __nv_bfloat16 lo = __float2bfloat16(val - __bfloat162float(hi));
                ch[(size_t)i * CDIM + lane] = hi;
                cl[(size_t)i * CDIM + lane] = lo;
            }
        }
    }
}

// ---------------------------------------------------------------------------
// launch
// ---------------------------------------------------------------------------
extern "C" void kernel_launch(void* const* d_in, const int* in_sizes, int n_in,
                              void* d_out, int out_size)
{
    const float* x          = (const float*)d_in[0];
    const float* mask       = (const float*)d_in[1];
    const float* qkv_w      = (const float*)d_in[2];
    const float* qkv_b      = (const float*)d_in[3];
    const float* proj_w     = (const float*)d_in[4];
    const float* proj_b     = (const float*)d_in[5];
    const float* bias_table = (const float*)d_in[6];
    const int*   rel_index  = (const int*)d_in[7];
    float* out = (float*)d_out;

    cudaFuncSetAttribute(gemm_mma_kernel<0>, cudaFuncAttributeMaxDynamicSharedMemorySize, GEMM_SMEM);
    cudaFuncSetAttribute(gemm_mma_kernel<1>, cudaFuncAttributeMaxDynamicSharedMemorySize, GEMM_SMEM);

    split_kernel<0><<<(TOKENS * CDIM / 4 + 255) / 256, 256>>>(x);
    split_kernel<1><<<(QKV_COLS * CDIM / 4 + 255) / 256, 256>>>(qkv_w);
    split_kernel<2><<<(CDIM * CDIM / 4 + 255) / 256, 256>>>(proj_w);
    prep_mb_kernel<<<(NWMASK * NHEAD * NN + 255) / 256, 256>>>(mask, bias_table, rel_index);

    // QKV GEMM
    dim3 g1(QKV_COLS / TN, TOKENS / TM);   // (9, 1568)
    gemm_mma_kernel<0><<<g1, 256, GEMM_SMEM>>>(qkv_b, nullptr);

    attn_kernel<<<BWIN * NHEAD, 256>>>();

    // Proj GEMM
    dim3 g2(CDIM / TN, TOKENS / TM);       // (3, 1568)
    gemm_mma_kernel<1><<<g2, 256, GEMM_SMEM>>>(proj_b, out);
}

// round 15
// speedup vs baseline: 1.4754x; 1.4754x over previous
#include <cuda_runtime.h>
#include <cuda_fp16.h>
#include <cuda_bf16.h>
#include <math.h>
#include <stdint.h>

// ---------------------------------------------------------------------------
// Problem constants
// ---------------------------------------------------------------------------
#define BWIN   4096
#define NTOK   49
#define CDIM   384
#define NHEAD  12
#define HD     32
#define NWMASK 64
#define TOKENS (BWIN * NTOK)   // 200704
#define QKV_COLS (3 * CDIM)    // 1152
#define NN (NTOK * NTOK)       // 2401

// Scratch (device globals; referenced ONLY from device code)
__device__ float g_q[(size_t)BWIN * NHEAD * NTOK * HD];
__device__ float g_k[(size_t)BWIN * NHEAD * NTOK * HD];
__device__ float g_v[(size_t)BWIN * NHEAD * NTOK * HD];
__device__ float g_mb[(size_t)NWMASK * NHEAD * NN];
__device__ __half g_x16[(size_t)TOKENS * CDIM];
__device__ __half g_wq16[(size_t)QKV_COLS * CDIM];
__device__ __half g_wp16[(size_t)CDIM * CDIM];
__device__ __half g_ctx16[(size_t)TOKENS * CDIM];

// ---------------------------------------------------------------------------
// helpers
// ---------------------------------------------------------------------------
__device__ __forceinline__ uint32_t smem_to_u32(const void* smem_ptr) {
    uint32_t addr;
    asm("{ .reg .u64 tmp; cvta.to.shared.u64 tmp, %1; cvt.u32.u64 %0, tmp; }"
        : "=r"(addr) : "l"(smem_ptr));
    return addr;
}

__device__ __forceinline__ void ldsm4(uint32_t r[4], uint32_t addr) {
    asm volatile("ldmatrix.sync.aligned.m8n8.x4.shared.b16 {%0,%1,%2,%3}, [%4];"
        : "=r"(r[0]), "=r"(r[1]), "=r"(r[2]), "=r"(r[3]) : "r"(addr));
}

__device__ __forceinline__ void mma_fp16(float c[4], const uint32_t a[4],
                                         uint32_t b0, uint32_t b1) {
    asm volatile(
        "mma.sync.aligned.m16n8k16.row.col.f32.f16.f16.f32 "
        "{%0,%1,%2,%3}, {%4,%5,%6,%7}, {%8,%9}, {%0,%1,%2,%3};"
        : "+f"(c[0]), "+f"(c[1]), "+f"(c[2]), "+f"(c[3])
        : "r"(a[0]), "r"(a[1]), "r"(a[2]), "r"(a[3]), "r"(b0), "r"(b1));
}

#define CP_ASYNC_16(dst, src) \
    asm volatile("cp.async.ca.shared.global [%0], [%1], 16;" \
        :: "r"(dst), "l"(src) : "memory")
#define CP_COMMIT() asm volatile("cp.async.commit_group;" ::: "memory")
#define CP_WAIT1()  asm volatile("cp.async.wait_group 1;" ::: "memory")
#define CP_WAIT0()  asm volatile("cp.async.wait_group 0;" ::: "memory")

// ---------------------------------------------------------------------------
// Prep: convert fp32 arrays to fp16
// ---------------------------------------------------------------------------
template<int WHICH>
__global__ __launch_bounds__(256) void cvt_kernel(const float* __restrict__ src)
{
    const size_t count = (WHICH == 0) ? (size_t)TOKENS * CDIM
                       : (WHICH == 1) ? (size_t)QKV_COLS * CDIM
                                      : (size_t)CDIM * CDIM;
    __half* __restrict__ dst = (WHICH == 0) ? g_x16 : (WHICH == 1) ? g_wq16 : g_wp16;

    const size_t i4 = (size_t)blockIdx.x * 256 + threadIdx.x;
    if (i4 * 4 >= count) return;
    float4 a = *(const float4*)&src[i4 * 4];
    __half h0 = __float2half(a.x), h1 = __float2half(a.y);
    __half h2 = __float2half(a.z), h3 = __float2half(a.w);
    uint2 p;
    p.x = (uint32_t)__half_as_ushort(h0) | ((uint32_t)__half_as_ushort(h1) << 16);
    p.y = (uint32_t)__half_as_ushort(h2) | ((uint32_t)__half_as_ushort(h3) << 16);
    *(uint2*)&dst[i4 * 4] = p;
}

// ---------------------------------------------------------------------------
// Prep: g_mb[w][h][i*49+j] = mask[w][i][j] + bias_table[rel_index[i][j]][h]
// ---------------------------------------------------------------------------
__global__ __launch_bounds__(256) void prep_mb_kernel(
    const float* __restrict__ mask,
    const float* __restrict__ bias_table,
    const int*   __restrict__ rel_index)
{
    const int idx = blockIdx.x * 256 + threadIdx.x;
    if (idx >= NWMASK * NHEAD * NN) return;
    const int ij = idx % NN;
    const int wh = idx / NN;
    const int h = wh % NHEAD;
    const int w = wh / NHEAD;
    g_mb[idx] = mask[(size_t)w * NN + ij] + bias_table[rel_index[ij] * NHEAD + h];
}

// ---------------------------------------------------------------------------
// GEMM: 128(M) x 128(N) tile, K chunks of 32, 2-stage cp.async, fp16 single.
// 8 warps: wm=wid&1 (M64), wn=wid>>1 (N32). 1 MMA term, fp32 accum.
// ROWSTR=40 halves (80B rows): 16B-aligned, ldsm conflict-free (proven R10).
// ---------------------------------------------------------------------------
#define TM 128
#define TN 128
#define KCH 32
#define NCH (CDIM / KCH)            // 12
#define ROWSTR 40                   // fp16 per smem row (80B)
#define BUF_A 0
#define BUF_B (128 * 80)            // 10240
#define STAGE (2 * 128 * 80)        // 20480
#define GEMM_SMEM (2 * STAGE)       // 40960

// MODE 0: A=g_x16, B=g_wq16, scatter to g_q/g_k/g_v (+bias, q scaled)
// MODE 1: A=g_ctx16, B=g_wp16, dense out (+bias)
template<int MODE>
__global__ __launch_bounds__(256) void gemm_mma_kernel(
    const float* __restrict__ bias,
    float* __restrict__ Cout)
{
    const __half* __restrict__ A = (MODE == 0) ? g_x16 : g_ctx16;
    const __half* __restrict__ B = (MODE == 0) ? g_wq16 : g_wp16;

    extern __shared__ char smem[];
    const uint32_t sb = smem_to_u32(smem);
    const int tid = threadIdx.x;
    const int wid = tid >> 5;
    const int lane = tid & 31;
    const int m0 = blockIdx.y * TM;
    const int n0 = blockIdx.x * TN;
    const int wm = wid & 1;
    const int wn = wid >> 1;
    const int g = lane >> 2;
    const int t = lane & 3;

    // cp.async coords: 128 rows x 64B (32 fp16) per tile = 512 x 16B chunks,
    // 2 per thread per tile. v = tid + 256*i -> row v>>2, quarter v&3.
    const int row0 = tid >> 2,        q0 = tid & 3;
    const int row1 = (tid + 256) >> 2, q1 = tid & 3;
    const uint32_t soff0 = (uint32_t)(row0 * 80 + q0 * 16);
    const uint32_t soff1 = (uint32_t)(row1 * 80 + q1 * 16);
    const size_t goff0 = (size_t)row0 * CDIM + q0 * 8;
    const size_t goff1 = (size_t)row1 * CDIM + q1 * 8;

    float acc[4][4][4];
#pragma unroll
    for (int i = 0; i < 4; i++)
#pragma unroll
        for (int j = 0; j < 4; j++)
#pragma unroll
            for (int k = 0; k < 4; k++) acc[i][j][k] = 0.f;

    // ldmatrix bases (within stage): A m16k16 x4; B n16k16 x4
    const uint32_t aAddrBase =
        ((uint32_t)((wm * 64 + (lane & 15)) * ROWSTR + (lane >> 4) * 8)) * 2;
    const uint32_t bAddrBase =
        ((uint32_t)((wn * 32 + (lane & 7) + ((lane >> 4) & 1) * 8) * ROWSTR
                    + ((lane >> 3) & 1) * 8)) * 2;

#define ISSUE_CHUNK(stb, k0) do { \
    CP_ASYNC_16((stb) + BUF_A + soff0, A + (size_t)m0 * CDIM + (k0) + goff0); \
    CP_ASYNC_16((stb) + BUF_A + soff1, A + (size_t)m0 * CDIM + (k0) + goff1); \
    CP_ASYNC_16((stb) + BUF_B + soff0, B + (size_t)n0 * CDIM + (k0) + goff0); \
    CP_ASYNC_16((stb) + BUF_B + soff1, B + (size_t)n0 * CDIM + (k0) + goff1); \
    CP_COMMIT(); \
} while (0)

    ISSUE_CHUNK(sb, 0);

    for (int c = 0; c < NCH; c++) {
        if (c + 1 < NCH) {
            ISSUE_CHUNK(sb + (uint32_t)((c + 1) & 1) * STAGE, (c + 1) * KCH);
            CP_WAIT1();
        } else {
            CP_WAIT0();
        }
        __syncthreads();

        const uint32_t stb = sb + (uint32_t)(c & 1) * STAGE;
#pragma unroll
        for (int kk = 0; kk < 2; kk++) {
            uint32_t bf[2][4];
#pragma unroll
            for (int nt = 0; nt < 2; nt++) {
                ldsm4(bf[nt], stb + BUF_B + bAddrBase
                      + (uint32_t)(nt * 16 * ROWSTR) * 2 + kk * 32);
            }
#pragma unroll
            for (int mf = 0; mf < 4; mf++) {
                uint32_t af[4];
                ldsm4(af, stb + BUF_A + aAddrBase
                      + (uint32_t)(mf * 16 * ROWSTR + kk * 16) * 2);
#pragma unroll
                for (int nt = 0; nt < 2; nt++) {
#pragma unroll
                    for (int nf = 0; nf < 2; nf++) {
                        mma_fp16(acc[mf][nt * 2 + nf], af,
                                 bf[nt][nf * 2], bf[nt][nf * 2 + 1]);
                    }
                }
            }
        }
        __syncthreads();
    }
#undef ISSUE_CHUNK

    const int rbase = m0 + wm * 64;
    const int colw = n0 + wn * 32;

#pragma unroll
    for (int mf = 0; mf < 4; mf++) {
#pragma unroll
        for (int nc = 0; nc < 4; nc++) {
            const int col = colw + nc * 8 + 2 * t;
            const float2 bs = *(const float2*)&bias[col];
            if (MODE == 0) {
                const int three = n0 / CDIM;
                const int colseg = col - three * CDIM;
                const int h = colseg >> 5;
                const int d = colseg & 31;
                float* __restrict__ dst = (three == 0) ? g_q : ((three == 1) ? g_k : g_v);
                const float sc = (three == 0) ? 0.17677669529663687f : 1.0f;
#pragma unroll
                for (int hf = 0; hf < 2; hf++) {
                    const int r = rbase + mf * 16 + g + hf * 8;
                    const int bw = r / NTOK;
                    const int n = r - bw * NTOK;
                    float2 o;
                    o.x = (acc[mf][nc][hf * 2 + 0] + bs.x) * sc;
                    o.y = (acc[mf][nc][hf * 2 + 1] + bs.y) * sc;
                    *(float2*)&dst[(((size_t)bw * NHEAD + h) * NTOK + n) * HD + d] = o;
                }
            } else {
#pragma unroll
                for (int hf = 0; hf < 2; hf++) {
                    const int r = rbase + mf * 16 + g + hf * 8;
                    float2 o;
                    o.x = acc[mf][nc][hf * 2 + 0] + bs.x;
                    o.y = acc[mf][nc][hf * 2 + 1] + bs.y;
                    *(float2*)&Cout[(size_t)r * CDIM + col] = o;
                }
            }
        }
    }
}

// ---------------------------------------------------------------------------
// Attention (R10 version — proven): row-major smem, register-blocked,
// fused mb table; ctx output now single fp16.
// ---------------------------------------------------------------------------
__global__ __launch_bounds__(256) void attn_kernel(void)
{
    const int bh = blockIdx.x;
    const int b = bh / NHEAD;
    const int h = bh - b * NHEAD;
    const int wmask = b & (NWMASK - 1);

    __shared__ float qs[52 * 33];   // rows 49..51 zeroed
    __shared__ float ks[NTOK * 33];
    __shared__ float vs[NTOK * 33];
    __shared__ float s[52 * 50];    // rows 49..51 zeroed

    const float* __restrict__ qg = g_q + (size_t)bh * NTOK * HD;
    const float* __restrict__ kg = g_k + (size_t)bh * NTOK * HD;
    const float* __restrict__ vg = g_v + (size_t)bh * NTOK * HD;
    const float* __restrict__ mb = g_mb + (size_t)(wmask * NHEAD + h) * NN;

    for (int idx = threadIdx.x; idx < NTOK * HD; idx += 256) {
        const int n = idx >> 5;
        const int d = idx & 31;
        qs[n * 33 + d] = qg[idx];
        ks[n * 33 + d] = kg[idx];
        vs[n * 33 + d] = vg[idx];
    }
    if (threadIdx.x < 99)  qs[49 * 33 + threadIdx.x] = 0.f;
    if (threadIdx.x < 150) s[49 * 50 + threadIdx.x] = 0.f;
    __syncthreads();

    const int warp = threadIdx.x >> 5;
    const int lane = threadIdx.x & 31;
    const int j1ok = (lane < NTOK - 32);

    for (int it = warp; it < 13; it += 8) {
        const int i0 = it * 4;
        float a0[4] = {0.f, 0.f, 0.f, 0.f};
        float a1[4] = {0.f, 0.f, 0.f, 0.f};
#pragma unroll
        for (int m = 0; m < HD; m++) {
            const float kv0 = ks[lane * 33 + m];
            const float kv1 = j1ok ? ks[(lane + 32) * 33 + m] : 0.f;
#pragma unroll
            for (int r = 0; r < 4; r++) {
                const float qv = qs[(i0 + r) * 33 + m];   // broadcast
                a0[r] += qv * kv0;
                a1[r] += qv * kv1;
            }
        }
#pragma unroll
        for (int r = 0; r < 4; r++) {
            const int i = i0 + r;
            if (i < NTOK) {
                s[i * 50 + lane] = a0[r] + mb[i * NTOK + lane];
                if (j1ok) s[i * 50 + lane + 32] = a1[r] + mb[i * NTOK + lane + 32];
            }
        }
    }
    __syncthreads();

    for (int i = warp; i < NTOK; i += 8) {
        float v0 = s[i * 50 + lane];
        float v1 = j1ok ? s[i * 50 + lane + 32] : -INFINITY;
        float mx = fmaxf(v0, v1);
#pragma unroll
        for (int o = 16; o > 0; o >>= 1)
            mx = fmaxf(mx, __shfl_xor_sync(0xFFFFFFFFu, mx, o));
        float e0 = __expf(v0 - mx);
        float e1 = j1ok ? __expf(v1 - mx) : 0.f;
        float sum = e0 + e1;
#pragma unroll
        for (int o = 16; o > 0; o >>= 1)
            sum += __shfl_xor_sync(0xFFFFFFFFu, sum, o);
        const float inv = 1.f / sum;
        s[i * 50 + lane] = e0 * inv;
        if (j1ok) s[i * 50 + lane + 32] = e1 * inv;
    }
    __syncthreads();

    __half* __restrict__ cg = g_ctx16 + ((size_t)b * NTOK) * CDIM + h * HD;
    for (int it = warp; it < 13; it += 8) {
        const int i0 = it * 4;
        float a[4] = {0.f, 0.f, 0.f, 0.f};
        for (int j = 0; j < NTOK; j++) {
            const float vv = vs[j * 33 + lane];
#pragma unroll
            for (int r = 0; r < 4; r++)
                a[r] += s[(i0 + r) * 50 + j] * vv;   // s broadcast
        }
#pragma unroll
        for (int r = 0; r < 4; r++) {
            const int i = i0 + r;
            if (i < NTOK) cg[(size_t)i * CDIM + lane] = __float2half(a[r]);
        }
    }
}

// ---------------------------------------------------------------------------
// launch
// ---------------------------------------------------------------------------
extern "C" void kernel_launch(void* const* d_in, const int* in_sizes, int n_in,
                              void* d_out, int out_size)
{
    const float* x          = (const float*)d_in[0];
    const float* mask       = (const float*)d_in[1];
    const float* qkv_w      = (const float*)d_in[2];
    const float* qkv_b      = (const float*)d_in[3];
    const float* proj_w     = (const float*)d_in[4];
    const float* proj_b     = (const float*)d_in[5];
    const float* bias_table = (const float*)d_in[6];
    const int*   rel_index  = (const int*)d_in[7];
    float* out = (float*)d_out;

    cudaFuncSetAttribute(gemm_mma_kernel<0>, cudaFuncAttributeMaxDynamicSharedMemorySize, GEMM_SMEM);
    cudaFuncSetAttribute(gemm_mma_kernel<1>, cudaFuncAttributeMaxDynamicSharedMemorySize, GEMM_SMEM);

    cvt_kernel<0><<<(TOKENS * CDIM / 4 + 255) / 256, 256>>>(x);
    cvt_kernel<1><<<(QKV_COLS * CDIM / 4 + 255) / 256, 256>>>(qkv_w);
    cvt_kernel<2><<<(CDIM * CDIM / 4 + 255) / 256, 256>>>(proj_w);
    prep_mb_kernel<<<(NWMASK * NHEAD * NN + 255) / 256, 256>>>(mask, bias_table, rel_index);

    // QKV GEMM
    dim3 g1(QKV_COLS / TN, TOKENS / TM);   // (9, 1568)
    gemm_mma_kernel<0><<<g1, 256, GEMM_SMEM>>>(qkv_b, nullptr);

    attn_kernel<<<BWIN * NHEAD, 256>>>();

    // Proj GEMM
    dim3 g2(CDIM / TN, TOKENS / TM);       // (3, 1568)
    gemm_mma_kernel<1><<<g2, 256, GEMM_SMEM>>>(proj_b, out);
}

// round 16
// speedup vs baseline: 1.8955x; 1.2848x over previous
#include <cuda_runtime.h>
#include <cuda_fp16.h>
#include <math.h>
#include <stdint.h>

// ---------------------------------------------------------------------------
// Problem constants
// ---------------------------------------------------------------------------
#define BWIN   4096
#define NTOK   49
#define CDIM   384
#define NHEAD  12
#define HD     32
#define NWMASK 64
#define TOKENS (BWIN * NTOK)   // 200704
#define QKV_COLS (3 * CDIM)    // 1152
#define NN (NTOK * NTOK)       // 2401

// Scratch (device globals; referenced ONLY from device code)
__device__ __half g_q16[(size_t)BWIN * NHEAD * NTOK * HD];
__device__ __half g_k16[(size_t)BWIN * NHEAD * NTOK * HD];
__device__ float  g_v[(size_t)BWIN * NHEAD * NTOK * HD];
__device__ float  g_mb[(size_t)NWMASK * NHEAD * NN];
__device__ __half g_x16[(size_t)TOKENS * CDIM];
__device__ __half g_wq16[(size_t)QKV_COLS * CDIM];
__device__ __half g_wp16[(size_t)CDIM * CDIM];
__device__ __half g_ctx16[(size_t)TOKENS * CDIM];

// ---------------------------------------------------------------------------
// helpers
// ---------------------------------------------------------------------------
__device__ __forceinline__ uint32_t smem_to_u32(const void* smem_ptr) {
    uint32_t addr;
    asm("{ .reg .u64 tmp; cvta.to.shared.u64 tmp, %1; cvt.u32.u64 %0, tmp; }"
        : "=r"(addr) : "l"(smem_ptr));
    return addr;
}

__device__ __forceinline__ void ldsm4(uint32_t r[4], uint32_t addr) {
    asm volatile("ldmatrix.sync.aligned.m8n8.x4.shared.b16 {%0,%1,%2,%3}, [%4];"
        : "=r"(r[0]), "=r"(r[1]), "=r"(r[2]), "=r"(r[3]) : "r"(addr));
}

__device__ __forceinline__ void mma_fp16(float c[4], const uint32_t a[4],
                                         uint32_t b0, uint32_t b1) {
    asm volatile(
        "mma.sync.aligned.m16n8k16.row.col.f32.f16.f16.f32 "
        "{%0,%1,%2,%3}, {%4,%5,%6,%7}, {%8,%9}, {%0,%1,%2,%3};"
        : "+f"(c[0]), "+f"(c[1]), "+f"(c[2]), "+f"(c[3])
        : "r"(a[0]), "r"(a[1]), "r"(a[2]), "r"(a[3]), "r"(b0), "r"(b1));
}

#define CP_ASYNC_16(dst, src) \
    asm volatile("cp.async.ca.shared.global [%0], [%1], 16;" \
        :: "r"(dst), "l"(src) : "memory")
#define CP_COMMIT() asm volatile("cp.async.commit_group;" ::: "memory")
#define CP_WAIT1()  asm volatile("cp.async.wait_group 1;" ::: "memory")
#define CP_WAIT0()  asm volatile("cp.async.wait_group 0;" ::: "memory")

// ---------------------------------------------------------------------------
// Prep: convert fp32 arrays to fp16
// ---------------------------------------------------------------------------
template<int WHICH>
__global__ __launch_bounds__(256) void cvt_kernel(const float* __restrict__ src)
{
    const size_t count = (WHICH == 0) ? (size_t)TOKENS * CDIM
                       : (WHICH == 1) ? (size_t)QKV_COLS * CDIM
                                      : (size_t)CDIM * CDIM;
    __half* __restrict__ dst = (WHICH == 0) ? g_x16 : (WHICH == 1) ? g_wq16 : g_wp16;

    const size_t i4 = (size_t)blockIdx.x * 256 + threadIdx.x;
    if (i4 * 4 >= count) return;
    float4 a = *(const float4*)&src[i4 * 4];
    __half h0 = __float2half(a.x), h1 = __float2half(a.y);
    __half h2 = __float2half(a.z), h3 = __float2half(a.w);
    uint2 p;
    p.x = (uint32_t)__half_as_ushort(h0) | ((uint32_t)__half_as_ushort(h1) << 16);
    p.y = (uint32_t)__half_as_ushort(h2) | ((uint32_t)__half_as_ushort(h3) << 16);
    *(uint2*)&dst[i4 * 4] = p;
}

// ---------------------------------------------------------------------------
// Prep: g_mb[w][h][i*49+j] = mask[w][i][j] + bias_table[rel_index[i][j]][h]
// ---------------------------------------------------------------------------
__global__ __launch_bounds__(256) void prep_mb_kernel(
    const float* __restrict__ mask,
    const float* __restrict__ bias_table,
    const int*   __restrict__ rel_index)
{
    const int idx = blockIdx.x * 256 + threadIdx.x;
    if (idx >= NWMASK * NHEAD * NN) return;
    const int ij = idx % NN;
    const int wh = idx / NN;
    const int h = wh % NHEAD;
    const int w = wh / NHEAD;
    g_mb[idx] = mask[(size_t)w * NN + ij] + bias_table[rel_index[ij] * NHEAD + h];
}

// ---------------------------------------------------------------------------
// GEMM (R15 proven): 128x128 tile, K=32 chunks, 2-stage cp.async, fp16 single.
// MODE 0: q/k written as fp16 (q scaled), v as fp32. MODE 1: dense fp32 out.
// ---------------------------------------------------------------------------
#define TM 128
#define TN 128
#define KCH 32
#define NCH (CDIM / KCH)            // 12
#define ROWSTR 40                   // fp16 per smem row (80B)
#define BUF_A 0
#define BUF_B (128 * 80)            // 10240
#define STAGE (2 * 128 * 80)        // 20480
#define GEMM_SMEM (2 * STAGE)       // 40960

template<int MODE>
__global__ __launch_bounds__(256) void gemm_mma_kernel(
    const float* __restrict__ bias,
    float* __restrict__ Cout)
{
    const __half* __restrict__ A = (MODE == 0) ? g_x16 : g_ctx16;
    const __half* __restrict__ B = (MODE == 0) ? g_wq16 : g_wp16;

    extern __shared__ char smem[];
    const uint32_t sb = smem_to_u32(smem);
    const int tid = threadIdx.x;
    const int wid = tid >> 5;
    const int lane = tid & 31;
    const int m0 = blockIdx.y * TM;
    const int n0 = blockIdx.x * TN;
    const int wm = wid & 1;
    const int wn = wid >> 1;
    const int g = lane >> 2;
    const int t = lane & 3;

    const int row0 = tid >> 2,         q0 = tid & 3;
    const int row1 = (tid + 256) >> 2, q1 = tid & 3;
    const uint32_t soff0 = (uint32_t)(row0 * 80 + q0 * 16);
    const uint32_t soff1 = (uint32_t)(row1 * 80 + q1 * 16);
    const size_t goff0 = (size_t)row0 * CDIM + q0 * 8;
    const size_t goff1 = (size_t)row1 * CDIM + q1 * 8;

    float acc[4][4][4];
#pragma unroll
    for (int i = 0; i < 4; i++)
#pragma unroll
        for (int j = 0; j < 4; j++)
#pragma unroll
            for (int k = 0; k < 4; k++) acc[i][j][k] = 0.f;

    const uint32_t aAddrBase =
        ((uint32_t)((wm * 64 + (lane & 15)) * ROWSTR + (lane >> 4) * 8)) * 2;
    const uint32_t bAddrBase =
        ((uint32_t)((wn * 32 + (lane & 7) + ((lane >> 4) & 1) * 8) * ROWSTR
                    + ((lane >> 3) & 1) * 8)) * 2;

#define ISSUE_CHUNK(stb, k0) do { \
    CP_ASYNC_16((stb) + BUF_A + soff0, A + (size_t)m0 * CDIM + (k0) + goff0); \
    CP_ASYNC_16((stb) + BUF_A + soff1, A + (size_t)m0 * CDIM + (k0) + goff1); \
    CP_ASYNC_16((stb) + BUF_B + soff0, B + (size_t)n0 * CDIM + (k0) + goff0); \
    CP_ASYNC_16((stb) + BUF_B + soff1, B + (size_t)n0 * CDIM + (k0) + goff1); \
    CP_COMMIT(); \
} while (0)

    ISSUE_CHUNK(sb, 0);

    for (int c = 0; c < NCH; c++) {
        if (c + 1 < NCH) {
            ISSUE_CHUNK(sb + (uint32_t)((c + 1) & 1) * STAGE, (c + 1) * KCH);
            CP_WAIT1();
        } else {
            CP_WAIT0();
        }
        __syncthreads();

        const uint32_t stb = sb + (uint32_t)(c & 1) * STAGE;
#pragma unroll
        for (int kk = 0; kk < 2; kk++) {
            uint32_t bf[2][4];
#pragma unroll
            for (int nt = 0; nt < 2; nt++) {
                ldsm4(bf[nt], stb + BUF_B + bAddrBase
                      + (uint32_t)(nt * 16 * ROWSTR) * 2 + kk * 32);
            }
#pragma unroll
            for (int mf = 0; mf < 4; mf++) {
                uint32_t af[4];
                ldsm4(af, stb + BUF_A + aAddrBase
                      + (uint32_t)(mf * 16 * ROWSTR + kk * 16) * 2);
#pragma unroll
                for (int nt = 0; nt < 2; nt++) {
#pragma unroll
                    for (int nf = 0; nf < 2; nf++) {
                        mma_fp16(acc[mf][nt * 2 + nf], af,
                                 bf[nt][nf * 2], bf[nt][nf * 2 + 1]);
                    }
                }
            }
        }
        __syncthreads();
    }
#undef ISSUE_CHUNK

    const int rbase = m0 + wm * 64;
    const int colw = n0 + wn * 32;

#pragma unroll
    for (int mf = 0; mf < 4; mf++) {
#pragma unroll
        for (int nc = 0; nc < 4; nc++) {
            const int col = colw + nc * 8 + 2 * t;
            const float2 bs = *(const float2*)&bias[col];
            if (MODE == 0) {
                const int three = n0 / CDIM;
                const int colseg = col - three * CDIM;
                const int h = colseg >> 5;
                const int d = colseg & 31;
                if (three <= 1) {
                    __half* __restrict__ dst16 = (three == 0) ? g_q16 : g_k16;
                    const float sc = (three == 0) ? 0.17677669529663687f : 1.0f;
#pragma unroll
                    for (int hf = 0; hf < 2; hf++) {
                        const int r = rbase + mf * 16 + g + hf * 8;
                        const int bw = r / NTOK;
                        const int n = r - bw * NTOK;
                        __half2 o = __floats2half2_rn(
                            (acc[mf][nc][hf * 2 + 0] + bs.x) * sc,
                            (acc[mf][nc][hf * 2 + 1] + bs.y) * sc);
                        *(__half2*)&dst16[(((size_t)bw * NHEAD + h) * NTOK + n) * HD + d] = o;
                    }
                } else {
#pragma unroll
                    for (int hf = 0; hf < 2; hf++) {
                        const int r = rbase + mf * 16 + g + hf * 8;
                        const int bw = r / NTOK;
                        const int n = r - bw * NTOK;
                        float2 o;
                        o.x = acc[mf][nc][hf * 2 + 0] + bs.x;
                        o.y = acc[mf][nc][hf * 2 + 1] + bs.y;
                        *(float2*)&g_v[(((size_t)bw * NHEAD + h) * NTOK + n) * HD + d] = o;
                    }
                }
            } else {
#pragma unroll
                for (int hf = 0; hf < 2; hf++) {
                    const int r = rbase + mf * 16 + g + hf * 8;
                    float2 o;
                    o.x = acc[mf][nc][hf * 2 + 0] + bs.x;
                    o.y = acc[mf][nc][hf * 2 + 1] + bs.y;
                    *(float2*)&Cout[(size_t)r * CDIM + col] = o;
                }
            }
        }
    }
}

// ---------------------------------------------------------------------------
// Attention via HMMA. One block per (window, head), 256 threads (8 warps).
// QK^T: M=64(pad) x N=64(pad) x K=32, q/k fp16 (stride 40).
// softmax fp32. AV: p split hi/lo fp16 (stride 72), v split hi/lo transposed
// (stride 72); 3-term HMMA. Pads contained by pre-zeroing ps/vT.
// ---------------------------------------------------------------------------
#define AQS 0                       // q: 64 x 40 fp16 = 5120 B
#define AKS 5120                    // k: 64 x 40 fp16 = 5120 B
#define AS32 10240                  // s: 64 x 64 f32 = 16384 B
#define APH 26624                   // p_hi: 64 x 72 fp16 = 9216 B
#define APL 35840                   // p_lo: 9216 B
#define AVH 45056                   // vT_hi: 32 x 72 fp16 = 4608 B
#define AVL 49664                   // vT_lo: 4608 B
#define ATT_SMEM 54272

__global__ __launch_bounds__(256) void attn_kernel(void)
{
    extern __shared__ char smem[];
    const uint32_t sb = smem_to_u32(smem);

    const int bh = blockIdx.x;
    const int b = bh / NHEAD;
    const int h = bh - b * NHEAD;
    const int wmask = b & (NWMASK - 1);

    const __half* __restrict__ qg = g_q16 + (size_t)bh * NTOK * HD;
    const __half* __restrict__ kg = g_k16 + (size_t)bh * NTOK * HD;
    const float*  __restrict__ vg = g_v + (size_t)bh * NTOK * HD;
    const float*  __restrict__ mb = g_mb + (size_t)(wmask * NHEAD + h) * NN;

    const int tid = threadIdx.x;
    const int wid = tid >> 5;
    const int lane = tid & 31;
    const int g = lane >> 2;
    const int t = lane & 3;

    // zero PH..VL (contiguous 27648 B = 6912 words)
    for (int z = tid; z < 6912; z += 256)
        ((uint32_t*)(smem + APH))[z] = 0u;

    // load q, k (fp16 pairs: 49*16 = 784 words each)
    for (int idx = tid; idx < NTOK * HD / 2; idx += 256) {
        const int n = idx >> 4;
        const int d2 = idx & 15;
        *(uint32_t*)(smem + AQS + n * 80 + d2 * 4) = ((const uint32_t*)qg)[idx];
        *(uint32_t*)(smem + AKS + n * 80 + d2 * 4) = ((const uint32_t*)kg)[idx];
    }
    // load v fp32, split hi/lo, store transposed [d][j]
    for (int idx = tid; idx < NTOK * HD; idx += 256) {
        const int j = idx >> 5;
        const int d = idx & 31;
        const float val = vg[idx];
        const __half hi = __float2half(val);
        const __half lo = __float2half(val - __half2float(hi));
        *(__half*)(smem + AVH + (d * 72 + j) * 2) = hi;
        *(__half*)(smem + AVL + (d * 72 + j) * 2) = lo;
    }
    __syncthreads();

    // ---- QK^T: warp (mf = wid&3, nh = wid>>2 covering 32 cols) ----
    {
        const int mf = wid & 3;
        const int nh = wid >> 2;
        float acc[4][4];
#pragma unroll
        for (int i = 0; i < 4; i++)
#pragma unroll
            for (int k = 0; k < 4; k++) acc[i][k] = 0.f;

        const uint32_t aBase = sb + AQS
            + (uint32_t)(((mf * 16 + (lane & 15)) * 40 + (lane >> 4) * 8) * 2);
        const uint32_t bBase = sb + AKS
            + (uint32_t)(((nh * 32 + (lane & 7) + ((lane >> 4) & 1) * 8) * 40
                          + ((lane >> 3) & 1) * 8) * 2);
#pragma unroll
        for (int kk = 0; kk < 2; kk++) {
            uint32_t af[4], bf0[4], bf1[4];
            ldsm4(af, aBase + kk * 32);
            ldsm4(bf0, bBase + kk * 32);
            ldsm4(bf1, bBase + 16 * 80 + kk * 32);
            mma_fp16(acc[0], af, bf0[0], bf0[1]);
            mma_fp16(acc[1], af, bf0[2], bf0[3]);
            mma_fp16(acc[2], af, bf1[0], bf1[1]);
            mma_fp16(acc[3], af, bf1[2], bf1[3]);
        }
        // store scores + mb into S32 (64-wide rows)
#pragma unroll
        for (int nf = 0; nf < 4; nf++) {
            const int j0 = nh * 32 + nf * 8 + 2 * t;
#pragma unroll
            for (int hf = 0; hf < 2; hf++) {
                const int i = mf * 16 + g + hf * 8;
                float2 o;
                o.x = acc[nf][hf * 2 + 0]
                    + ((i < NTOK && j0 < NTOK) ? mb[i * NTOK + j0] : 0.f);
                o.y = acc[nf][hf * 2 + 1]
                    + ((i < NTOK && j0 + 1 < NTOK) ? mb[i * NTOK + j0 + 1] : 0.f);
                *(float2*)(smem + AS32 + (i * 64 + j0) * 4) = o;
            }
        }
    }
    __syncthreads();

    // ---- softmax (rows i<49), write p hi/lo fp16 ----
    const int j1ok = (lane < NTOK - 32);
    for (int i = wid; i < NTOK; i += 8) {
        const float* srow = (const float*)(smem + AS32 + i * 256);
        float v0 = srow[lane];
        float v1 = j1ok ? srow[lane + 32] : -INFINITY;
        float mx = fmaxf(v0, v1);
#pragma unroll
        for (int o = 16; o > 0; o >>= 1)
            mx = fmaxf(mx, __shfl_xor_sync(0xFFFFFFFFu, mx, o));
        float e0 = __expf(v0 - mx);
        float e1 = j1ok ? __expf(v1 - mx) : 0.f;
        float sum = e0 + e1;
#pragma unroll
        for (int o = 16; o > 0; o >>= 1)
            sum += __shfl_xor_sync(0xFFFFFFFFu, sum, o);
        const float inv = 1.f / sum;
        const float p0 = e0 * inv;
        const __half p0h = __float2half(p0);
        *(__half*)(smem + APH + (i * 72 + lane) * 2) = p0h;
        *(__half*)(smem + APL + (i * 72 + lane) * 2) =
            __float2half(p0 - __half2float(p0h));
        if (j1ok) {
            const float p1 = e1 * inv;
            const __half p1h = __float2half(p1);
            *(__half*)(smem + APH + (i * 72 + lane + 32) * 2) = p1h;
            *(__half*)(smem + APL + (i * 72 + lane + 32) * 2) =
                __float2half(p1 - __half2float(p1h));
        }
    }
    __syncthreads();

    // ---- AV: warp (mf = wid&3, nh2 = wid>>2 covering 16 of 32 d-cols) ----
    {
        const int mf = wid & 3;
        const int nh2 = wid >> 2;
        float acc[2][4];
#pragma unroll
        for (int i = 0; i < 2; i++)
#pragma unroll
            for (int k = 0; k < 4; k++) acc[i][k] = 0.f;

        const uint32_t aRow = (uint32_t)(((mf * 16 + (lane & 15)) * 72
                                          + (lane >> 4) * 8) * 2);
        const uint32_t bRow = (uint32_t)(((nh2 * 16 + (lane & 7) + ((lane >> 4) & 1) * 8) * 72
                                          + ((lane >> 3) & 1) * 8) * 2);
        const uint32_t aBaseH = sb + APH + aRow;
        const uint32_t aBaseL = sb + APL + aRow;
        const uint32_t bBaseH = sb + AVH + bRow;
        const uint32_t bBaseL = sb + AVL + bRow;
#pragma unroll
        for (int kk = 0; kk < 4; kk++) {
            uint32_t ph[4], pl[4], vh[4], vl[4];
            ldsm4(ph, aBaseH + kk * 32);
            ldsm4(pl, aBaseL + kk * 32);
            ldsm4(vh, bBaseH + kk * 32);
            ldsm4(vl, bBaseL + kk * 32);
#pragma unroll
            for (int nf = 0; nf < 2; nf++) {
                mma_fp16(acc[nf], ph, vh[nf * 2], vh[nf * 2 + 1]);
                mma_fp16(acc[nf], ph, vl[nf * 2], vl[nf * 2 + 1]);
                mma_fp16(acc[nf], pl, vh[nf * 2], vh[nf * 2 + 1]);
            }
        }
        // write ctx fp16
        __half* __restrict__ cg = g_ctx16 + ((size_t)b * NTOK) * CDIM + h * HD;
#pragma unroll
        for (int nf = 0; nf < 2; nf++) {
            const int d0 = nh2 * 16 + nf * 8 + 2 * t;
#pragma unroll
            for (int hf = 0; hf < 2; hf++) {
                const int i = mf * 16 + g + hf * 8;
                if (i < NTOK) {
                    __half2 o = __floats2half2_rn(acc[nf][hf * 2 + 0],
                                                  acc[nf][hf * 2 + 1]);
                    *(__half2*)&cg[(size_t)i * CDIM + d0] = o;
                }
            }
        }
    }
}

// ---------------------------------------------------------------------------
// launch
// ---------------------------------------------------------------------------
extern "C" void kernel_launch(void* const* d_in, const int* in_sizes, int n_in,
                              void* d_out, int out_size)
{
    const float* x          = (const float*)d_in[0];
    const float* mask       = (const float*)d_in[1];
    const float* qkv_w      = (const float*)d_in[2];
    const float* qkv_b      = (const float*)d_in[3];
    const float* proj_w     = (const float*)d_in[4];
    const float* proj_b     = (const float*)d_in[5];
    const float* bias_table = (const float*)d_in[6];
    const int*   rel_index  = (const int*)d_in[7];
    float* out = (float*)d_out;

    cudaFuncSetAttribute(gemm_mma_kernel<0>, cudaFuncAttributeMaxDynamicSharedMemorySize, GEMM_SMEM);
    cudaFuncSetAttribute(gemm_mma_kernel<1>, cudaFuncAttributeMaxDynamicSharedMemorySize, GEMM_SMEM);
    cudaFuncSetAttribute(attn_kernel, cudaFuncAttributeMaxDynamicSharedMemorySize, ATT_SMEM);

    cvt_kernel<0><<<(TOKENS * CDIM / 4 + 255) / 256, 256>>>(x);
    cvt_kernel<1><<<(QKV_COLS * CDIM / 4 + 255) / 256, 256>>>(qkv_w);
    cvt_kernel<2><<<(CDIM * CDIM / 4 + 255) / 256, 256>>>(proj_w);
    prep_mb_kernel<<<(NWMASK * NHEAD * NN + 255) / 256, 256>>>(mask, bias_table, rel_index);

    // QKV GEMM
    dim3 g1(QKV_COLS / TN, TOKENS / TM);   // (9, 1568)
    gemm_mma_kernel<0><<<g1, 256, GEMM_SMEM>>>(qkv_b, nullptr);

    attn_kernel<<<BWIN * NHEAD, 256, ATT_SMEM>>>();

    // Proj GEMM
    dim3 g2(CDIM / TN, TOKENS / TM);       // (3, 1568)
    gemm_mma_kernel<1><<<g2, 256, GEMM_SMEM>>>(proj_b, out);
}